// round 15
// baseline (speedup 1.0000x reference)
#include <cuda_runtime.h>
#include <cuda_fp16.h>
#include <cstdint>
#include <mma.h>

using namespace nvcuda;

#define SEQ   2048
#define DIMSZ 4096
#define NHEAD 32
#define HDIM  128

// Scratch (device globals: allocation-free per harness rules)
__device__ __half g_qh[(size_t)SEQ * DIMSZ];             // fp16 Q (post-rope)
__device__ __half g_kh[(size_t)SEQ * DIMSZ];             // fp16 K (post-rope)
__device__ __half g_vh[(size_t)SEQ * DIMSZ];             // fp16 V
__device__ __half g_xh[(size_t)SEQ * DIMSZ];             // fp16 x
__device__ __half g_wh[(size_t)4 * DIMSZ * DIMSZ];       // fp16 wq,wk,wv,wo
__device__ __half g_oh[(size_t)SEQ * DIMSZ];             // fp16 attention output

__device__ __forceinline__ void cp16(void* s, const void* g) {
    unsigned int sa = (unsigned int)__cvta_generic_to_shared(s);
    asm volatile("cp.async.cg.shared.global [%0], [%1], 16;" :: "r"(sa), "l"(g));
}
#define CP_COMMIT() asm volatile("cp.async.commit_group;")
#define CP_WAITG(n) asm volatile("cp.async.wait_group %0;" :: "n"(n))

// ---------------------------------------------------------------------------
// Fused fp16 conversion of x (z=0) and the 4 weights (z=1..4).
// ---------------------------------------------------------------------------
#define W4 (DIMSZ * DIMSZ / 4)
#define X4 (SEQ * DIMSZ / 4)
__global__ void cvt_all(const float4* __restrict__ x,
                        const float4* __restrict__ w0, const float4* __restrict__ w1,
                        const float4* __restrict__ w2, const float4* __restrict__ w3)
{
    int z = blockIdx.z;
    int i = blockIdx.x * blockDim.x + threadIdx.x;
    const float4* src;
    __half2* dst;
    int n;
    if (z == 0)      { src = x;  dst = (__half2*)g_xh;                               n = X4; }
    else if (z == 1) { src = w0; dst = (__half2*)(g_wh);                             n = W4; }
    else if (z == 2) { src = w1; dst = (__half2*)(g_wh + (size_t)1 * DIMSZ * DIMSZ); n = W4; }
    else if (z == 3) { src = w2; dst = (__half2*)(g_wh + (size_t)2 * DIMSZ * DIMSZ); n = W4; }
    else             { src = w3; dst = (__half2*)(g_wh + (size_t)3 * DIMSZ * DIMSZ); n = W4; }
    if (i >= n) return;
    float4 v = src[i];
    dst[2 * i]     = __floats2half2_rn(v.x, v.y);
    dst[2 * i + 1] = __floats2half2_rn(v.z, v.w);
}

// ---------------------------------------------------------------------------
// GEMM v5: block tile 128x64, BK=32, 3-stage cp.async, 256 thr = 8 warps,
// warp grid 4x2 (32x32 each). Small footprint (44.5 KB smem, <=85 regs via
// launch_bounds(256,3)) -> 3 CTAs/SM = 24 warps to hide LDSM/HMMA latency.
// ---------------------------------------------------------------------------
#define GM 2048
#define GN 4096
#define GK 4096
#define BKH 32
#define NTH (GK / BKH)   // 128
#define STAGES 3
#define LDAH 40          // halves per A row (32+8): 80B, 16B-multiple
#define LDBH 72          // halves per B row (64+8): 144B, 16B-multiple
#define ASTAGEH (128 * LDAH)
#define BSTAGEH (BKH * LDBH)
#define GEMM_SMEM_BYTES (STAGES * (ASTAGEH + BSTAGEH) * 2)   // 44,544 B

__device__ __forceinline__ void issue_stage(const __half* __restrict__ A,
                                            const __half* __restrict__ B,
                                            __half* As, __half* Bs,
                                            int bm, int bn, int kk, int tid)
{
    // A tile 128x32 halves: 4 chunks/row, 512 chunks, 2/thread
#pragma unroll
    for (int i = 0; i < 2; i++) {
        int c = tid + i * 256;
        int r = c >> 2, k8 = (c & 3) << 3;
        cp16(&As[r * LDAH + k8], A + (size_t)(bm + r) * GK + kk + k8);
    }
    // B tile 32x64 halves: 8 chunks/row, 256 chunks, 1/thread
    {
        int c = tid;
        if (c < 256) {
            int r = c >> 3, c8 = (c & 7) << 3;
            cp16(&Bs[r * LDBH + c8], B + (size_t)(kk + r) * GN + bn + c8);
        }
    }
}

__device__ __forceinline__ void gemm_mainloop(
    const __half* __restrict__ A, const __half* __restrict__ B, __half* sm,
    wmma::fragment<wmma::accumulator, 16, 16, 16, float> (&acc)[2][2],
    int bm, int bn, int wr, int wc, int tid)
{
    __half* As = sm;
    __half* Bs = sm + STAGES * ASTAGEH;

#pragma unroll
    for (int i = 0; i < 2; i++)
#pragma unroll
        for (int j = 0; j < 2; j++) wmma::fill_fragment(acc[i][j], 0.0f);

    issue_stage(A, B, As, Bs, bm, bn, 0, tid);
    CP_COMMIT();
    issue_stage(A, B, As + ASTAGEH, Bs + BSTAGEH, bm, bn, BKH, tid);
    CP_COMMIT();

    for (int t = 0; t < NTH; t++) {
        CP_WAITG(1);
        __syncthreads();

        int nk = t + 2;
        if (nk < NTH) {
            int buf = nk % STAGES;
            issue_stage(A, B, As + buf * ASTAGEH, Bs + buf * BSTAGEH, bm, bn, nk * BKH, tid);
        }
        CP_COMMIT();

        const __half* Ac = As + (t % STAGES) * ASTAGEH;
        const __half* Bc = Bs + (t % STAGES) * BSTAGEH;
#pragma unroll
        for (int ks = 0; ks < 2; ks++) {     // 2 x k16 = BK 32
            wmma::fragment<wmma::matrix_a, 16, 16, 16, __half, wmma::row_major> a[2];
            wmma::fragment<wmma::matrix_b, 16, 16, 16, __half, wmma::row_major> b[2];
#pragma unroll
            for (int i = 0; i < 2; i++)
                wmma::load_matrix_sync(a[i], &Ac[(wr + i * 16) * LDAH + ks * 16], LDAH);
#pragma unroll
            for (int j = 0; j < 2; j++)
                wmma::load_matrix_sync(b[j], &Bc[(ks * 16) * LDBH + wc + j * 16], LDBH);
#pragma unroll
            for (int i = 0; i < 2; i++)
#pragma unroll
                for (int j = 0; j < 2; j++)
                    wmma::mma_sync(acc[i][j], a[i], b[j], acc[i][j]);
        }
    }
}

// ---------------------------------------------------------------------------
// QKV GEMM with FUSED rope (z=0,1) / fp16 convert (z=2) epilogue.
// N-tile = 64 cols = half a head (head = bn>>7, head-col base = bn&64).
// Rope pairs are adjacent even/odd cols; accumulator e-pair mapping proven in
// R12-14: row = r0 + 8*((e&3)>=2), col = c0 + (e&1) + 8*(e>=4), pairs (e,e+1).
// ---------------------------------------------------------------------------
__global__ __launch_bounds__(256, 3) void gemm_qkv(const float* __restrict__ fc,
                                                   const float* __restrict__ fs)
{
    extern __shared__ __half smh[];
    const int z    = blockIdx.z;
    const int tid  = threadIdx.x;
    const int w    = tid >> 5;
    const int lane = tid & 31;
    const int bm   = blockIdx.x * 128;
    const int bn   = blockIdx.y * 64;
    const int wr   = (w >> 1) * 32;
    const int wc   = (w & 1) * 32;

    wmma::fragment<wmma::accumulator, 16, 16, 16, float> acc[2][2];
    gemm_mainloop(g_xh, g_wh + (size_t)z * DIMSZ * DIMSZ, smh, acc, bm, bn, wr, wc, tid);

    __syncthreads();   // mainloop smem reads done; safe to overlay

    // Stage cos/sin for rows bm..bm+127, this block's 32 pairs (16 KB x2).
    float* fcs = (float*)smh;            // [128][32]
    float* fsn = fcs + 128 * 32;         // [128][32]
    if (z < 2) {
        const int pairbase = (bn & 64) >> 1;        // 0 or 32
        for (int i = tid; i < 1024; i += 256) {     // 128 rows x 8 float4
            int r = i >> 3, p4 = (i & 7) << 2;
            *(float4*)&fcs[r * 32 + p4] = *(const float4*)&fc[(size_t)(bm + r) * 64 + pairbase + p4];
            *(float4*)&fsn[r * 32 + p4] = *(const float4*)&fs[(size_t)(bm + r) * 64 + pairbase + p4];
        }
    }
    __syncthreads();

    __half* dst = (z == 0) ? g_qh : (z == 1) ? g_kh : g_vh;
    const int r0 = lane >> 2;
    const int c0 = (lane & 3) * 2;
#pragma unroll
    for (int i16 = 0; i16 < 2; i16++) {
#pragma unroll
        for (int j = 0; j < 2; j++) {
#pragma unroll
            for (int e = 0; e < 8; e += 2) {
                int row_l = wr + i16 * 16 + r0 + (((e & 3) >= 2) ? 8 : 0);
                int col_l = wc + j * 16 + c0 + ((e >= 4) ? 8 : 0);   // even
                float v0 = acc[i16][j].x[e];
                float v1 = acc[i16][j].x[e + 1];
                float o0, o1;
                if (z < 2) {
                    float cc = fcs[row_l * 32 + (col_l >> 1)];
                    float ss = fsn[row_l * 32 + (col_l >> 1)];
                    o0 = v0 * cc - v1 * ss;
                    o1 = v0 * ss + v1 * cc;
                } else {
                    o0 = v0; o1 = v1;
                }
                *(__half2*)&dst[(size_t)(bm + row_l) * DIMSZ + bn + col_l] =
                    __floats2half2_rn(o0, o1);
            }
        }
    }
}

// ---------------------------------------------------------------------------
// Output GEMM: fp32 store to d_out. (Profiled: 4th launch.)
// ---------------------------------------------------------------------------
__global__ __launch_bounds__(256, 3) void gemm_out(float* __restrict__ C)
{
    extern __shared__ __half smh[];
    const int tid = threadIdx.x;
    const int w   = tid >> 5;
    const int bm  = blockIdx.x * 128;
    const int bn  = blockIdx.y * 64;
    const int wr  = (w >> 1) * 32;
    const int wc  = (w & 1) * 32;

    wmma::fragment<wmma::accumulator, 16, 16, 16, float> acc[2][2];
    gemm_mainloop(g_oh, g_wh + (size_t)3 * DIMSZ * DIMSZ, smh, acc, bm, bn, wr, wc, tid);

#pragma unroll
    for (int i = 0; i < 2; i++)
#pragma unroll
        for (int j = 0; j < 2; j++)
            wmma::store_matrix_sync(C + (size_t)(bm + wr + i * 16) * GN + bn + wc + j * 16,
                                    acc[i][j], GN, wmma::mem_row_major);
}

// ---------------------------------------------------------------------------
// Flash attention v6 (unchanged from R13/14, proven): fp16 datapath,
// q-tile 64, k-tile 64, double-buffered K/V, register O + softmax state.
// ---------------------------------------------------------------------------
#define BKT 64
#define LDQH2 136   // halves per row (128+8)
#define LDS_S 68    // fp32 scores (64+4)
#define LDPH 72     // fp16 P (64+8)
#define FLASH_HALVES (5 * 64 * LDQH2)
#define FLASH_SMEM_BYTES (FLASH_HALVES * 2 + (64 * LDS_S + 128) * 4 + 64 * LDPH * 2)

__global__ __launch_bounds__(256, 2) void flash_attn()
{
    extern __shared__ __half smh[];
    __half* Qs = smh;                        // 64 x LDQH2
    __half* Ks = Qs + 64 * LDQH2;            // 2 x 64 x LDQH2
    __half* Vs = Ks + 2 * 64 * LDQH2;        // 2 x 64 x LDQH2
    float*  Ss = (float*)(Vs + 2 * 64 * LDQH2);   // 64 x LDS_S fp32
    float*  lrow = Ss + 64 * LDS_S;
    float*  arow = lrow + 64;
    __half* Ps = (__half*)(arow + 64);       // 64 x LDPH fp16

    const int qb   = (gridDim.x - 1) - blockIdx.x;
    const int h    = blockIdx.y;
    const int tid  = threadIdx.x;
    const int w    = tid >> 5;
    const int lane = tid & 31;
    const float scale = 0.08838834764831845f;  // 1/sqrt(128)

    const __half* Qg = g_qh + (size_t)qb * 64 * DIMSZ + h * HDIM;
    const __half* Kh = g_kh + (size_t)h * HDIM;
    const __half* Vh = g_vh + (size_t)h * HDIM;

    const int owr = (w >> 2) * 32;
    const int owc = (w & 3) * 32;
    wmma::fragment<wmma::accumulator, 16, 16, 16, float> oacc[2][2];
#pragma unroll
    for (int i = 0; i < 2; i++)
#pragma unroll
        for (int j = 0; j < 2; j++) wmma::fill_fragment(oacc[i][j], 0.0f);

    const int srow = tid >> 2;
    const int ssub = tid & 3;
    float m_state = -1e30f;
    float l_state = 0.0f;

#pragma unroll
    for (int i = 0; i < 4; i++) {
        int idx = tid + i * 256;
        int r = idx >> 4, c8 = (idx & 15) << 3;
        cp16(&Qs[r * LDQH2 + c8], Qg + (size_t)r * DIMSZ + c8);
        cp16(&Ks[r * LDQH2 + c8], Kh + (size_t)r * DIMSZ + c8);
        cp16(&Vs[r * LDQH2 + c8], Vh + (size_t)r * DIMSZ + c8);
    }
    CP_COMMIT();

    const int ntiles = qb + 1;

    for (int kt = 0; kt < ntiles; kt++) {
        const int buf = kt & 1;

        if (kt + 1 < ntiles) {
            __half* Kn = Ks + (buf ^ 1) * 64 * LDQH2;
            __half* Vn = Vs + (buf ^ 1) * 64 * LDQH2;
            const __half* Kg = Kh + (size_t)(kt + 1) * 64 * DIMSZ;
            const __half* Vg = Vh + (size_t)(kt + 1) * 64 * DIMSZ;
#pragma unroll
            for (int i = 0; i < 4; i++) {
                int idx = tid + i * 256;
                int r = idx >> 4, c8 = (idx & 15) << 3;
                cp16(&Kn[r * LDQH2 + c8], Kg + (size_t)r * DIMSZ + c8);
                cp16(&Vn[r * LDQH2 + c8], Vg + (size_t)r * DIMSZ + c8);
            }
            CP_COMMIT();
            CP_WAITG(1);
        } else {
            CP_WAITG(0);
        }
        __syncthreads();

        const __half* Kc = Ks + buf * 64 * LDQH2;
        const __half* Vc = Vs + buf * 64 * LDQH2;

        // S = scale * Q @ K^T : warp grid 4x2, each warp 16 rows x 32 cols
        {
            const int wr = (w >> 1) * 16;
            const int wc = (w & 1) * 32;
            wmma::fragment<wmma::accumulator, 16, 16, 16, float> c[2];
            wmma::fill_fragment(c[0], 0.0f);
            wmma::fill_fragment(c[1], 0.0f);
#pragma unroll
            for (int ks = 0; ks < 8; ks++) {
                wmma::fragment<wmma::matrix_a, 16, 16, 16, __half, wmma::row_major> a;
                wmma::load_matrix_sync(a, &Qs[wr * LDQH2 + ks * 16], LDQH2);
#pragma unroll
                for (int j = 0; j < 2; j++) {
                    wmma::fragment<wmma::matrix_b, 16, 16, 16, __half, wmma::col_major> b;
                    wmma::load_matrix_sync(b, &Kc[(wc + j * 16) * LDQH2 + ks * 16], LDQH2);
                    wmma::mma_sync(c[j], a, b, c[j]);
                }
            }
#pragma unroll
            for (int j = 0; j < 2; j++) {
#pragma unroll
                for (int t = 0; t < c[j].num_elements; t++) c[j].x[t] *= scale;
                wmma::store_matrix_sync(&Ss[wr * LDS_S + wc + j * 16], c[j], LDS_S,
                                        wmma::mem_row_major);
            }
        }
        __syncthreads();

        // Online softmax: 4 threads/row, 16 cols each; P -> fp16 Ps.
        {
            int lim = qb * 64 + srow - kt * 64;
            int smax = lim + 1;
            if (smax > BKT) smax = BKT;
            if (smax < 0)   smax = 0;
            float mloc = -1e30f;
            int c0 = ssub * 16;
#pragma unroll
            for (int c = 0; c < 16; c++) {
                int cc = c0 + c;
                if (cc < smax) mloc = fmaxf(mloc, Ss[srow * LDS_S + cc]);
            }
#pragma unroll
            for (int o = 1; o < 4; o <<= 1)
                mloc = fmaxf(mloc, __shfl_xor_sync(0xffffffffu, mloc, o));
            float mn = fmaxf(m_state, mloc);
            float alpha = __expf(m_state - mn);
            float lsum = 0.0f;
#pragma unroll
            for (int c = 0; c < 16; c += 2) {
                int cc = c0 + c;
                float p0 = (cc < smax)     ? __expf(Ss[srow * LDS_S + cc] - mn)     : 0.0f;
                float p1 = (cc + 1 < smax) ? __expf(Ss[srow * LDS_S + cc + 1] - mn) : 0.0f;
                *(__half2*)&Ps[srow * LDPH + cc] = __floats2half2_rn(p0, p1);
                lsum += p0 + p1;
            }
#pragma unroll
            for (int o = 1; o < 4; o <<= 1)
                lsum += __shfl_xor_sync(0xffffffffu, lsum, o);
            l_state = l_state * alpha + lsum;
            m_state = mn;
            if (ssub == 0) arow[srow] = alpha;
        }
        __syncthreads();

        // Rescale O accumulator in registers
        {
            const int r0 = lane >> 2;
#pragma unroll
            for (int i = 0; i < 2; i++) {
                float a0 = arow[owr + i * 16 + r0];
                float a1 = arow[owr + i * 16 + r0 + 8];
#pragma unroll
                for (int j = 0; j < 2; j++)
#pragma unroll
                    for (int e = 0; e < 8; e++)
                        oacc[i][j].x[e] *= ((e & 3) >= 2) ? a1 : a0;
            }
        }

        // O += P @ V : warp grid 2x4, each warp 32x32, 4 k-steps of 16
        {
#pragma unroll
            for (int ks = 0; ks < 4; ks++) {
                wmma::fragment<wmma::matrix_a, 16, 16, 16, __half, wmma::row_major> a[2];
                wmma::fragment<wmma::matrix_b, 16, 16, 16, __half, wmma::row_major> b[2];
#pragma unroll
                for (int i = 0; i < 2; i++)
                    wmma::load_matrix_sync(a[i], &Ps[(owr + i * 16) * LDPH + ks * 16], LDPH);
#pragma unroll
                for (int j = 0; j < 2; j++)
                    wmma::load_matrix_sync(b[j], &Vc[(ks * 16) * LDQH2 + owc + j * 16], LDQH2);
#pragma unroll
                for (int i = 0; i < 2; i++)
#pragma unroll
                    for (int j = 0; j < 2; j++)
                        wmma::mma_sync(oacc[i][j], a[i], b[j], oacc[i][j]);
            }
        }
        __syncthreads();
    }

    if (ssub == 0) lrow[srow] = l_state;
    __syncthreads();

    __half* Og = g_oh + (size_t)qb * 64 * DIMSZ + h * HDIM;
    {
        const int r0 = lane >> 2;
        const int c0 = (lane & 3) * 2;
#pragma unroll
        for (int i = 0; i < 2; i++) {
            float inv0 = 1.0f / lrow[owr + i * 16 + r0];
            float inv1 = 1.0f / lrow[owr + i * 16 + r0 + 8];
#pragma unroll
            for (int j = 0; j < 2; j++) {
#pragma unroll
                for (int e = 0; e < 8; e++) {
                    float v = oacc[i][j].x[e] * (((e & 3) >= 2) ? inv1 : inv0);
                    int row = owr + i * 16 + r0 + (((e & 3) >= 2) ? 8 : 0);
                    int col = owc + j * 16 + c0 + (e & 1) + ((e >= 4) ? 8 : 0);
                    Og[(size_t)row * DIMSZ + col] = __float2half_rn(v);
                }
            }
        }
    }
}

// ---------------------------------------------------------------------------
extern "C" void kernel_launch(void* const* d_in, const int* in_sizes, int n_in,
                              void* d_out, int out_size)
{
    const float* x  = (const float*)d_in[0];
    const float* wq = (const float*)d_in[1];
    const float* wk = (const float*)d_in[2];
    const float* wv = (const float*)d_in[3];
    const float* wo = (const float*)d_in[4];
    const float* fc = (const float*)d_in[5];
    const float* fs = (const float*)d_in[6];
    float* out = (float*)d_out;

    cudaFuncSetAttribute(gemm_qkv, cudaFuncAttributeMaxDynamicSharedMemorySize,
                         GEMM_SMEM_BYTES);
    cudaFuncSetAttribute(gemm_out, cudaFuncAttributeMaxDynamicSharedMemorySize,
                         GEMM_SMEM_BYTES);
    cudaFuncSetAttribute(flash_attn, cudaFuncAttributeMaxDynamicSharedMemorySize,
                         FLASH_SMEM_BYTES);

    // 1: fused fp16 conversion (x + 4 weights)
    dim3 cgrid((W4 + 255) / 256, 1, 5);
    cvt_all<<<cgrid, 256>>>((const float4*)x, (const float4*)wq, (const float4*)wk,
                            (const float4*)wv, (const float4*)wo);

    // 2: QKV projections with fused rope + fp16 epilogue (128x64 tiles)
    dim3 qkv_grid(GM / 128, GN / 64, 3);
    gemm_qkv<<<qkv_grid, 256, GEMM_SMEM_BYTES>>>(fc, fs);

    // 3: flash attention v6
    flash_attn<<<dim3(SEQ / 64, NHEAD), 256, FLASH_SMEM_BYTES>>>();

    // 4: output projection (4th launch -> ncu profiles new GEMM config)
    dim3 ogrid(GM / 128, GN / 64);
    gemm_out<<<ogrid, 256, GEMM_SMEM_BYTES>>>(out);
}

// round 16
// speedup vs baseline: 1.0118x; 1.0118x over previous
#include <cuda_runtime.h>
#include <cuda_fp16.h>
#include <cstdint>
#include <mma.h>

using namespace nvcuda;

#define SEQ   2048
#define DIMSZ 4096
#define NHEAD 32
#define HDIM  128

// Scratch (device globals: allocation-free per harness rules)
__device__ __half g_qh[(size_t)SEQ * DIMSZ];             // fp16 Q (post-rope)
__device__ __half g_kh[(size_t)SEQ * DIMSZ];             // fp16 K (post-rope)
__device__ __half g_vh[(size_t)SEQ * DIMSZ];             // fp16 V
__device__ __half g_xh[(size_t)SEQ * DIMSZ];             // fp16 x
__device__ __half g_wh[(size_t)4 * DIMSZ * DIMSZ];       // fp16 wq,wk,wv,wo
__device__ __half g_oh[(size_t)SEQ * DIMSZ];             // fp16 attention output

__device__ __forceinline__ void cp16(void* s, const void* g) {
    unsigned int sa = (unsigned int)__cvta_generic_to_shared(s);
    asm volatile("cp.async.cg.shared.global [%0], [%1], 16;" :: "r"(sa), "l"(g));
}
#define CP_COMMIT() asm volatile("cp.async.commit_group;")
#define CP_WAITG(n) asm volatile("cp.async.wait_group %0;" :: "n"(n))

// ---------------------------------------------------------------------------
// Fused fp16 conversion of x (z=0) and the 4 weights (z=1..4).
// ---------------------------------------------------------------------------
#define W4 (DIMSZ * DIMSZ / 4)
#define X4 (SEQ * DIMSZ / 4)
__global__ void cvt_all(const float4* __restrict__ x,
                        const float4* __restrict__ w0, const float4* __restrict__ w1,
                        const float4* __restrict__ w2, const float4* __restrict__ w3)
{
    int z = blockIdx.z;
    int i = blockIdx.x * blockDim.x + threadIdx.x;
    const float4* src;
    __half2* dst;
    int n;
    if (z == 0)      { src = x;  dst = (__half2*)g_xh;                               n = X4; }
    else if (z == 1) { src = w0; dst = (__half2*)(g_wh);                             n = W4; }
    else if (z == 2) { src = w1; dst = (__half2*)(g_wh + (size_t)1 * DIMSZ * DIMSZ); n = W4; }
    else if (z == 3) { src = w2; dst = (__half2*)(g_wh + (size_t)2 * DIMSZ * DIMSZ); n = W4; }
    else             { src = w3; dst = (__half2*)(g_wh + (size_t)3 * DIMSZ * DIMSZ); n = W4; }
    if (i >= n) return;
    float4 v = src[i];
    dst[2 * i]     = __floats2half2_rn(v.x, v.y);
    dst[2 * i + 1] = __floats2half2_rn(v.z, v.w);
}

// ---------------------------------------------------------------------------
// GEMM v6: block tile 256x128, BK=64, 3-stage cp.async, 256 thr = 8 warps,
// warp grid 4x2 -> warp tile 64x64 (acc[4][4]). Bigger warp tile cuts LDSM
// bytes/MAC by 33% vs 32x64 (R14) -- smem crossbar is the measured limiter
// (L1 45-55% in R14/R15 profiles). 159 KB smem -> 1 CTA/SM, ~212 regs.
// ---------------------------------------------------------------------------
#define GM 2048
#define GN 4096
#define GK 4096
#define BM 256
#define BN 128
#define BKH 64
#define NTH (GK / BKH)   // 64
#define STAGES 3
#define LDAH 72          // halves per A row (64+8)
#define LDBH 136         // halves per B row (128+8)
#define ASTAGEH (BM * LDAH)
#define BSTAGEH (BKH * LDBH)
#define GEMM_SMEM_BYTES (STAGES * (ASTAGEH + BSTAGEH) * 2)   // 162,816 B

__device__ __forceinline__ void issue_stage(const __half* __restrict__ A,
                                            const __half* __restrict__ B,
                                            __half* As, __half* Bs,
                                            int bm, int bn, int kk, int tid)
{
    // A tile 256x64 halves: 8 chunks/row, 2048 chunks, 8/thread
#pragma unroll
    for (int i = 0; i < 8; i++) {
        int c = tid + i * 256;
        int r = c >> 3, k8 = (c & 7) << 3;
        cp16(&As[r * LDAH + k8], A + (size_t)(bm + r) * GK + kk + k8);
    }
    // B tile 64x128 halves: 16 chunks/row, 1024 chunks, 4/thread
#pragma unroll
    for (int i = 0; i < 4; i++) {
        int c = tid + i * 256;
        int r = c >> 4, c8 = (c & 15) << 3;
        cp16(&Bs[r * LDBH + c8], B + (size_t)(kk + r) * GN + bn + c8);
    }
}

__device__ __forceinline__ void gemm_mainloop(
    const __half* __restrict__ A, const __half* __restrict__ B, __half* sm,
    wmma::fragment<wmma::accumulator, 16, 16, 16, float> (&acc)[4][4],
    int bm, int bn, int wr, int wc, int tid)
{
    __half* As = sm;
    __half* Bs = sm + STAGES * ASTAGEH;

#pragma unroll
    for (int i = 0; i < 4; i++)
#pragma unroll
        for (int j = 0; j < 4; j++) wmma::fill_fragment(acc[i][j], 0.0f);

    issue_stage(A, B, As, Bs, bm, bn, 0, tid);
    CP_COMMIT();
    issue_stage(A, B, As + ASTAGEH, Bs + BSTAGEH, bm, bn, BKH, tid);
    CP_COMMIT();

    for (int t = 0; t < NTH; t++) {
        CP_WAITG(1);
        __syncthreads();

        int nk = t + 2;
        if (nk < NTH) {
            int buf = nk % STAGES;
            issue_stage(A, B, As + buf * ASTAGEH, Bs + buf * BSTAGEH, bm, bn, nk * BKH, tid);
        }
        CP_COMMIT();

        const __half* Ac = As + (t % STAGES) * ASTAGEH;
        const __half* Bc = Bs + (t % STAGES) * BSTAGEH;
#pragma unroll
        for (int ks = 0; ks < 4; ks++) {     // 4 x k16 = BK 64
            wmma::fragment<wmma::matrix_a, 16, 16, 16, __half, wmma::row_major> a[4];
            wmma::fragment<wmma::matrix_b, 16, 16, 16, __half, wmma::row_major> b[4];
#pragma unroll
            for (int i = 0; i < 4; i++)
                wmma::load_matrix_sync(a[i], &Ac[(wr + i * 16) * LDAH + ks * 16], LDAH);
#pragma unroll
            for (int j = 0; j < 4; j++)
                wmma::load_matrix_sync(b[j], &Bc[(ks * 16) * LDBH + wc + j * 16], LDBH);
#pragma unroll
            for (int i = 0; i < 4; i++)
#pragma unroll
                for (int j = 0; j < 4; j++)
                    wmma::mma_sync(acc[i][j], a[i], b[j], acc[i][j]);
        }
    }
}

// ---------------------------------------------------------------------------
// QKV GEMM with FUSED rope (z=0,1) / fp16 convert (z=2) epilogue.
// N-tile (128 cols) == one full head; rope pair = local col / 2. cos/sin
// read directly via __ldg (1 MB table, L2-resident, heavily reused).
// Accumulator e-pair mapping proven R12-14: row = r0 + 8*((e&3)>=2),
// col = c0 + (e&1) + 8*(e>=4); adjacent pairs (e, e+1) for even e.
// ---------------------------------------------------------------------------
__global__ __launch_bounds__(256) void gemm_qkv(const float* __restrict__ fc,
                                                const float* __restrict__ fs)
{
    extern __shared__ __half smh[];
    const int z    = blockIdx.z;
    const int tid  = threadIdx.x;
    const int w    = tid >> 5;
    const int lane = tid & 31;
    const int bm   = blockIdx.x * BM;
    const int bn   = blockIdx.y * BN;
    const int wr   = (w >> 1) * 64;
    const int wc   = (w & 1) * 64;

    wmma::fragment<wmma::accumulator, 16, 16, 16, float> acc[4][4];
    gemm_mainloop(g_xh, g_wh + (size_t)z * DIMSZ * DIMSZ, smh, acc, bm, bn, wr, wc, tid);

    __half* dst = (z == 0) ? g_qh : (z == 1) ? g_kh : g_vh;
    const int r0 = lane >> 2;
    const int c0 = (lane & 3) * 2;
#pragma unroll
    for (int i16 = 0; i16 < 4; i16++) {
#pragma unroll
        for (int j = 0; j < 4; j++) {
#pragma unroll
            for (int e = 0; e < 8; e += 2) {
                int row_l = wr + i16 * 16 + r0 + (((e & 3) >= 2) ? 8 : 0);
                int col_l = wc + j * 16 + c0 + ((e >= 4) ? 8 : 0);   // even
                float v0 = acc[i16][j].x[e];
                float v1 = acc[i16][j].x[e + 1];
                float o0, o1;
                if (z < 2) {
                    size_t fidx = (size_t)(bm + row_l) * 64 + (col_l >> 1);
                    float cc = __ldg(&fc[fidx]);
                    float ss = __ldg(&fs[fidx]);
                    o0 = v0 * cc - v1 * ss;
                    o1 = v0 * ss + v1 * cc;
                } else {
                    o0 = v0; o1 = v1;
                }
                *(__half2*)&dst[(size_t)(bm + row_l) * DIMSZ + bn + col_l] =
                    __floats2half2_rn(o0, o1);
            }
        }
    }
}

// ---------------------------------------------------------------------------
// Output GEMM: fp32 store to d_out. (Profiled: 4th launch.)
// ---------------------------------------------------------------------------
__global__ __launch_bounds__(256) void gemm_out(float* __restrict__ C)
{
    extern __shared__ __half smh[];
    const int tid = threadIdx.x;
    const int w   = tid >> 5;
    const int bm  = blockIdx.x * BM;
    const int bn  = blockIdx.y * BN;
    const int wr  = (w >> 1) * 64;
    const int wc  = (w & 1) * 64;

    wmma::fragment<wmma::accumulator, 16, 16, 16, float> acc[4][4];
    gemm_mainloop(g_oh, g_wh + (size_t)3 * DIMSZ * DIMSZ, smh, acc, bm, bn, wr, wc, tid);

#pragma unroll
    for (int i = 0; i < 4; i++)
#pragma unroll
        for (int j = 0; j < 4; j++)
            wmma::store_matrix_sync(C + (size_t)(bm + wr + i * 16) * GN + bn + wc + j * 16,
                                    acc[i][j], GN, wmma::mem_row_major);
}

// ---------------------------------------------------------------------------
// Flash attention v6 (unchanged from R13/14, proven): fp16 datapath,
// q-tile 64, k-tile 64, double-buffered K/V, register O + softmax state.
// ---------------------------------------------------------------------------
#define BKT 64
#define LDQH2 136   // halves per row (128+8)
#define LDS_S 68    // fp32 scores (64+4)
#define LDPH 72     // fp16 P (64+8)
#define FLASH_HALVES (5 * 64 * LDQH2)
#define FLASH_SMEM_BYTES (FLASH_HALVES * 2 + (64 * LDS_S + 128) * 4 + 64 * LDPH * 2)

__global__ __launch_bounds__(256, 2) void flash_attn()
{
    extern __shared__ __half smh[];
    __half* Qs = smh;                        // 64 x LDQH2
    __half* Ks = Qs + 64 * LDQH2;            // 2 x 64 x LDQH2
    __half* Vs = Ks + 2 * 64 * LDQH2;        // 2 x 64 x LDQH2
    float*  Ss = (float*)(Vs + 2 * 64 * LDQH2);   // 64 x LDS_S fp32
    float*  lrow = Ss + 64 * LDS_S;
    float*  arow = lrow + 64;
    __half* Ps = (__half*)(arow + 64);       // 64 x LDPH fp16

    const int qb   = (gridDim.x - 1) - blockIdx.x;
    const int h    = blockIdx.y;
    const int tid  = threadIdx.x;
    const int w    = tid >> 5;
    const int lane = tid & 31;
    const float scale = 0.08838834764831845f;  // 1/sqrt(128)

    const __half* Qg = g_qh + (size_t)qb * 64 * DIMSZ + h * HDIM;
    const __half* Kh = g_kh + (size_t)h * HDIM;
    const __half* Vh = g_vh + (size_t)h * HDIM;

    const int owr = (w >> 2) * 32;
    const int owc = (w & 3) * 32;
    wmma::fragment<wmma::accumulator, 16, 16, 16, float> oacc[2][2];
#pragma unroll
    for (int i = 0; i < 2; i++)
#pragma unroll
        for (int j = 0; j < 2; j++) wmma::fill_fragment(oacc[i][j], 0.0f);

    const int srow = tid >> 2;
    const int ssub = tid & 3;
    float m_state = -1e30f;
    float l_state = 0.0f;

#pragma unroll
    for (int i = 0; i < 4; i++) {
        int idx = tid + i * 256;
        int r = idx >> 4, c8 = (idx & 15) << 3;
        cp16(&Qs[r * LDQH2 + c8], Qg + (size_t)r * DIMSZ + c8);
        cp16(&Ks[r * LDQH2 + c8], Kh + (size_t)r * DIMSZ + c8);
        cp16(&Vs[r * LDQH2 + c8], Vh + (size_t)r * DIMSZ + c8);
    }
    CP_COMMIT();

    const int ntiles = qb + 1;

    for (int kt = 0; kt < ntiles; kt++) {
        const int buf = kt & 1;

        if (kt + 1 < ntiles) {
            __half* Kn = Ks + (buf ^ 1) * 64 * LDQH2;
            __half* Vn = Vs + (buf ^ 1) * 64 * LDQH2;
            const __half* Kg = Kh + (size_t)(kt + 1) * 64 * DIMSZ;
            const __half* Vg = Vh + (size_t)(kt + 1) * 64 * DIMSZ;
#pragma unroll
            for (int i = 0; i < 4; i++) {
                int idx = tid + i * 256;
                int r = idx >> 4, c8 = (idx & 15) << 3;
                cp16(&Kn[r * LDQH2 + c8], Kg + (size_t)r * DIMSZ + c8);
                cp16(&Vn[r * LDQH2 + c8], Vg + (size_t)r * DIMSZ + c8);
            }
            CP_COMMIT();
            CP_WAITG(1);
        } else {
            CP_WAITG(0);
        }
        __syncthreads();

        const __half* Kc = Ks + buf * 64 * LDQH2;
        const __half* Vc = Vs + buf * 64 * LDQH2;

        // S = scale * Q @ K^T : warp grid 4x2, each warp 16 rows x 32 cols
        {
            const int wr = (w >> 1) * 16;
            const int wc = (w & 1) * 32;
            wmma::fragment<wmma::accumulator, 16, 16, 16, float> c[2];
            wmma::fill_fragment(c[0], 0.0f);
            wmma::fill_fragment(c[1], 0.0f);
#pragma unroll
            for (int ks = 0; ks < 8; ks++) {
                wmma::fragment<wmma::matrix_a, 16, 16, 16, __half, wmma::row_major> a;
                wmma::load_matrix_sync(a, &Qs[wr * LDQH2 + ks * 16], LDQH2);
#pragma unroll
                for (int j = 0; j < 2; j++) {
                    wmma::fragment<wmma::matrix_b, 16, 16, 16, __half, wmma::col_major> b;
                    wmma::load_matrix_sync(b, &Kc[(wc + j * 16) * LDQH2 + ks * 16], LDQH2);
                    wmma::mma_sync(c[j], a, b, c[j]);
                }
            }
#pragma unroll
            for (int j = 0; j < 2; j++) {
#pragma unroll
                for (int t = 0; t < c[j].num_elements; t++) c[j].x[t] *= scale;
                wmma::store_matrix_sync(&Ss[wr * LDS_S + wc + j * 16], c[j], LDS_S,
                                        wmma::mem_row_major);
            }
        }
        __syncthreads();

        // Online softmax: 4 threads/row, 16 cols each; P -> fp16 Ps.
        {
            int lim = qb * 64 + srow - kt * 64;
            int smax = lim + 1;
            if (smax > BKT) smax = BKT;
            if (smax < 0)   smax = 0;
            float mloc = -1e30f;
            int c0 = ssub * 16;
#pragma unroll
            for (int c = 0; c < 16; c++) {
                int cc = c0 + c;
                if (cc < smax) mloc = fmaxf(mloc, Ss[srow * LDS_S + cc]);
            }
#pragma unroll
            for (int o = 1; o < 4; o <<= 1)
                mloc = fmaxf(mloc, __shfl_xor_sync(0xffffffffu, mloc, o));
            float mn = fmaxf(m_state, mloc);
            float alpha = __expf(m_state - mn);
            float lsum = 0.0f;
#pragma unroll
            for (int c = 0; c < 16; c += 2) {
                int cc = c0 + c;
                float p0 = (cc < smax)     ? __expf(Ss[srow * LDS_S + cc] - mn)     : 0.0f;
                float p1 = (cc + 1 < smax) ? __expf(Ss[srow * LDS_S + cc + 1] - mn) : 0.0f;
                *(__half2*)&Ps[srow * LDPH + cc] = __floats2half2_rn(p0, p1);
                lsum += p0 + p1;
            }
#pragma unroll
            for (int o = 1; o < 4; o <<= 1)
                lsum += __shfl_xor_sync(0xffffffffu, lsum, o);
            l_state = l_state * alpha + lsum;
            m_state = mn;
            if (ssub == 0) arow[srow] = alpha;
        }
        __syncthreads();

        // Rescale O accumulator in registers
        {
            const int r0 = lane >> 2;
#pragma unroll
            for (int i = 0; i < 2; i++) {
                float a0 = arow[owr + i * 16 + r0];
                float a1 = arow[owr + i * 16 + r0 + 8];
#pragma unroll
                for (int j = 0; j < 2; j++)
#pragma unroll
                    for (int e = 0; e < 8; e++)
                        oacc[i][j].x[e] *= ((e & 3) >= 2) ? a1 : a0;
            }
        }

        // O += P @ V : warp grid 2x4, each warp 32x32, 4 k-steps of 16
        {
#pragma unroll
            for (int ks = 0; ks < 4; ks++) {
                wmma::fragment<wmma::matrix_a, 16, 16, 16, __half, wmma::row_major> a[2];
                wmma::fragment<wmma::matrix_b, 16, 16, 16, __half, wmma::row_major> b[2];
#pragma unroll
                for (int i = 0; i < 2; i++)
                    wmma::load_matrix_sync(a[i], &Ps[(owr + i * 16) * LDPH + ks * 16], LDPH);
#pragma unroll
                for (int j = 0; j < 2; j++)
                    wmma::load_matrix_sync(b[j], &Vc[(ks * 16) * LDQH2 + owc + j * 16], LDQH2);
#pragma unroll
                for (int i = 0; i < 2; i++)
#pragma unroll
                    for (int j = 0; j < 2; j++)
                        wmma::mma_sync(oacc[i][j], a[i], b[j], oacc[i][j]);
            }
        }
        __syncthreads();
    }

    if (ssub == 0) lrow[srow] = l_state;
    __syncthreads();

    __half* Og = g_oh + (size_t)qb * 64 * DIMSZ + h * HDIM;
    {
        const int r0 = lane >> 2;
        const int c0 = (lane & 3) * 2;
#pragma unroll
        for (int i = 0; i < 2; i++) {
            float inv0 = 1.0f / lrow[owr + i * 16 + r0];
            float inv1 = 1.0f / lrow[owr + i * 16 + r0 + 8];
#pragma unroll
            for (int j = 0; j < 2; j++) {
#pragma unroll
                for (int e = 0; e < 8; e++) {
                    float v = oacc[i][j].x[e] * (((e & 3) >= 2) ? inv1 : inv0);
                    int row = owr + i * 16 + r0 + (((e & 3) >= 2) ? 8 : 0);
                    int col = owc + j * 16 + c0 + (e & 1) + ((e >= 4) ? 8 : 0);
                    Og[(size_t)row * DIMSZ + col] = __float2half_rn(v);
                }
            }
        }
    }
}

// ---------------------------------------------------------------------------
extern "C" void kernel_launch(void* const* d_in, const int* in_sizes, int n_in,
                              void* d_out, int out_size)
{
    const float* x  = (const float*)d_in[0];
    const float* wq = (const float*)d_in[1];
    const float* wk = (const float*)d_in[2];
    const float* wv = (const float*)d_in[3];
    const float* wo = (const float*)d_in[4];
    const float* fc = (const float*)d_in[5];
    const float* fs = (const float*)d_in[6];
    float* out = (float*)d_out;

    cudaFuncSetAttribute(gemm_qkv, cudaFuncAttributeMaxDynamicSharedMemorySize,
                         GEMM_SMEM_BYTES);
    cudaFuncSetAttribute(gemm_out, cudaFuncAttributeMaxDynamicSharedMemorySize,
                         GEMM_SMEM_BYTES);
    cudaFuncSetAttribute(flash_attn, cudaFuncAttributeMaxDynamicSharedMemorySize,
                         FLASH_SMEM_BYTES);

    // 1: fused fp16 conversion (x + 4 weights)
    dim3 cgrid((W4 + 255) / 256, 1, 5);
    cvt_all<<<cgrid, 256>>>((const float4*)x, (const float4*)wq, (const float4*)wk,
                            (const float4*)wv, (const float4*)wo);

    // 2: QKV projections with fused rope + fp16 epilogue (256x128 tiles)
    dim3 qkv_grid(GM / BM, GN / BN, 3);
    gemm_qkv<<<qkv_grid, 256, GEMM_SMEM_BYTES>>>(fc, fs);

    // 3: flash attention v6
    flash_attn<<<dim3(SEQ / 64, NHEAD), 256, FLASH_SMEM_BYTES>>>();

    // 4: output projection (4th launch -> ncu profiles new GEMM config)
    dim3 ogrid(GM / BM, GN / BN);
    gemm_out<<<ogrid, 256, GEMM_SMEM_BYTES>>>(out);
}

// round 17
// speedup vs baseline: 1.2012x; 1.1872x over previous
#include <cuda_runtime.h>
#include <cuda_fp16.h>
#include <cstdint>
#include <mma.h>

using namespace nvcuda;

#define SEQ   2048
#define DIMSZ 4096
#define NHEAD 32
#define HDIM  128

// Scratch (device globals: allocation-free per harness rules)
__device__ __half g_qh[(size_t)SEQ * DIMSZ];             // fp16 Q (post-rope)
__device__ __half g_kh[(size_t)SEQ * DIMSZ];             // fp16 K (post-rope)
__device__ __half g_vh[(size_t)SEQ * DIMSZ];             // fp16 V
__device__ __half g_xh[(size_t)SEQ * DIMSZ];             // fp16 x
__device__ __half g_wh[(size_t)4 * DIMSZ * DIMSZ];       // fp16 wq,wk,wv,wo
__device__ __half g_oh[(size_t)SEQ * DIMSZ];             // fp16 attention output

__device__ __forceinline__ void cp16(void* s, const void* g) {
    unsigned int sa = (unsigned int)__cvta_generic_to_shared(s);
    asm volatile("cp.async.cg.shared.global [%0], [%1], 16;" :: "r"(sa), "l"(g));
}
#define CP_COMMIT() asm volatile("cp.async.commit_group;")
#define CP_WAITG(n) asm volatile("cp.async.wait_group %0;" :: "n"(n))

// ---------------------------------------------------------------------------
// Fused fp16 conversion of x (z=0) and the 4 weights (z=1..4).
// ---------------------------------------------------------------------------
#define W4 (DIMSZ * DIMSZ / 4)
#define X4 (SEQ * DIMSZ / 4)
__global__ void cvt_all(const float4* __restrict__ x,
                        const float4* __restrict__ w0, const float4* __restrict__ w1,
                        const float4* __restrict__ w2, const float4* __restrict__ w3)
{
    int z = blockIdx.z;
    int i = blockIdx.x * blockDim.x + threadIdx.x;
    const float4* src;
    __half2* dst;
    int n;
    if (z == 0)      { src = x;  dst = (__half2*)g_xh;                               n = X4; }
    else if (z == 1) { src = w0; dst = (__half2*)(g_wh);                             n = W4; }
    else if (z == 2) { src = w1; dst = (__half2*)(g_wh + (size_t)1 * DIMSZ * DIMSZ); n = W4; }
    else if (z == 3) { src = w2; dst = (__half2*)(g_wh + (size_t)2 * DIMSZ * DIMSZ); n = W4; }
    else             { src = w3; dst = (__half2*)(g_wh + (size_t)3 * DIMSZ * DIMSZ); n = W4; }
    if (i >= n) return;
    float4 v = src[i];
    dst[2 * i]     = __floats2half2_rn(v.x, v.y);
    dst[2 * i + 1] = __floats2half2_rn(v.z, v.w);
}

// ---------------------------------------------------------------------------
// GEMM (R14 config, best measured: 232us): block 128x128, BK=64, 3-stage
// cp.async, 256 thr, warp grid 4x2 (32x64), launch_bounds(256,2).
// ---------------------------------------------------------------------------
#define GM 2048
#define GN 4096
#define GK 4096
#define BKH 64
#define NTH (GK / BKH)   // 64
#define STAGES 3
#define LDAH 72
#define LDBH 136
#define ASTAGEH (128 * LDAH)
#define BSTAGEH (BKH * LDBH)
#define GEMM_SMEM_BYTES (STAGES * (ASTAGEH + BSTAGEH) * 2)   // 107.5 KB

__device__ __forceinline__ void issue_stage(const __half* __restrict__ A,
                                            const __half* __restrict__ B,
                                            __half* As, __half* Bs,
                                            int bm, int bn, int kk, int tid)
{
#pragma unroll
    for (int i = 0; i < 4; i++) {
        int c = tid + i * 256;
        int r = c >> 3, k8 = (c & 7) << 3;
        cp16(&As[r * LDAH + k8], A + (size_t)(bm + r) * GK + kk + k8);
    }
#pragma unroll
    for (int i = 0; i < 4; i++) {
        int c = tid + i * 256;
        int r = c >> 4, c8 = (c & 15) << 3;
        cp16(&Bs[r * LDBH + c8], B + (size_t)(kk + r) * GN + bn + c8);
    }
}

__device__ __forceinline__ void gemm_mainloop(
    const __half* __restrict__ A, const __half* __restrict__ B, __half* sm,
    wmma::fragment<wmma::accumulator, 16, 16, 16, float> (&acc)[2][4],
    int bm, int bn, int wr, int wc, int tid)
{
    __half* As = sm;
    __half* Bs = sm + STAGES * ASTAGEH;

#pragma unroll
    for (int i = 0; i < 2; i++)
#pragma unroll
        for (int j = 0; j < 4; j++) wmma::fill_fragment(acc[i][j], 0.0f);

    issue_stage(A, B, As, Bs, bm, bn, 0, tid);
    CP_COMMIT();
    issue_stage(A, B, As + ASTAGEH, Bs + BSTAGEH, bm, bn, BKH, tid);
    CP_COMMIT();

    for (int t = 0; t < NTH; t++) {
        CP_WAITG(1);
        __syncthreads();

        int nk = t + 2;
        if (nk < NTH) {
            int buf = nk % STAGES;
            issue_stage(A, B, As + buf * ASTAGEH, Bs + buf * BSTAGEH, bm, bn, nk * BKH, tid);
        }
        CP_COMMIT();

        const __half* Ac = As + (t % STAGES) * ASTAGEH;
        const __half* Bc = Bs + (t % STAGES) * BSTAGEH;
#pragma unroll
        for (int ks = 0; ks < 4; ks++) {
            wmma::fragment<wmma::matrix_a, 16, 16, 16, __half, wmma::row_major> a[2];
            wmma::fragment<wmma::matrix_b, 16, 16, 16, __half, wmma::row_major> b[4];
#pragma unroll
            for (int i = 0; i < 2; i++)
                wmma::load_matrix_sync(a[i], &Ac[(wr + i * 16) * LDAH + ks * 16], LDAH);
#pragma unroll
            for (int j = 0; j < 4; j++)
                wmma::load_matrix_sync(b[j], &Bc[(ks * 16) * LDBH + wc + j * 16], LDBH);
#pragma unroll
            for (int i = 0; i < 2; i++)
#pragma unroll
                for (int j = 0; j < 4; j++)
                    wmma::mma_sync(acc[i][j], a[i], b[j], acc[i][j]);
        }
    }
}

// ---------------------------------------------------------------------------
// QKV GEMM with FUSED rope (z=0,1) / fp16 convert (z=2) epilogue (R14).
// ---------------------------------------------------------------------------
__global__ __launch_bounds__(256, 2) void gemm_qkv(const float* __restrict__ fc,
                                                   const float* __restrict__ fs)
{
    extern __shared__ __half smh[];
    const int z    = blockIdx.z;
    const int tid  = threadIdx.x;
    const int w    = tid >> 5;
    const int lane = tid & 31;
    const int bm   = blockIdx.x * 128;
    const int bn   = blockIdx.y * 128;
    const int wr   = (w >> 1) * 32;
    const int wc   = (w & 1) * 64;

    wmma::fragment<wmma::accumulator, 16, 16, 16, float> acc[2][4];
    gemm_mainloop(g_xh, g_wh + (size_t)z * DIMSZ * DIMSZ, smh, acc, bm, bn, wr, wc, tid);

    __syncthreads();   // mainloop smem reads done; safe to overlay

    float* fcs = (float*)smh;            // [128][64]
    float* fsn = fcs + 128 * 64;         // [128][64]
    if (z < 2) {
        const float4* fc4 = (const float4*)fc;
        const float4* fs4 = (const float4*)fs;
        for (int i = tid; i < 2048; i += 256) {
            ((float4*)fcs)[i] = fc4[bm * 16 + i];
            ((float4*)fsn)[i] = fs4[bm * 16 + i];
        }
    }
    __syncthreads();

    __half* dst = (z == 0) ? g_qh : (z == 1) ? g_kh : g_vh;
    const int r0 = lane >> 2;
    const int c0 = (lane & 3) * 2;
#pragma unroll
    for (int i16 = 0; i16 < 2; i16++) {
#pragma unroll
        for (int j = 0; j < 4; j++) {
#pragma unroll
            for (int e = 0; e < 8; e += 2) {
                int row_l = wr + i16 * 16 + r0 + (((e & 3) >= 2) ? 8 : 0);
                int col_l = wc + j * 16 + c0 + ((e >= 4) ? 8 : 0);   // even
                float v0 = acc[i16][j].x[e];
                float v1 = acc[i16][j].x[e + 1];
                float o0, o1;
                if (z < 2) {
                    float cc = fcs[row_l * 64 + (col_l >> 1)];
                    float ss = fsn[row_l * 64 + (col_l >> 1)];
                    o0 = v0 * cc - v1 * ss;
                    o1 = v0 * ss + v1 * cc;
                } else {
                    o0 = v0; o1 = v1;
                }
                *(__half2*)&dst[(size_t)(bm + row_l) * DIMSZ + bn + col_l] =
                    __floats2half2_rn(o0, o1);
            }
        }
    }
}

__global__ __launch_bounds__(256, 2) void gemm_out(float* __restrict__ C)
{
    extern __shared__ __half smh[];
    const int tid = threadIdx.x;
    const int w   = tid >> 5;
    const int bm  = blockIdx.x * 128;
    const int bn  = blockIdx.y * 128;
    const int wr  = (w >> 1) * 32;
    const int wc  = (w & 1) * 64;

    wmma::fragment<wmma::accumulator, 16, 16, 16, float> acc[2][4];
    gemm_mainloop(g_oh, g_wh + (size_t)3 * DIMSZ * DIMSZ, smh, acc, bm, bn, wr, wc, tid);

#pragma unroll
    for (int i = 0; i < 2; i++)
#pragma unroll
        for (int j = 0; j < 4; j++)
            wmma::store_matrix_sync(C + (size_t)(bm + wr + i * 16) * GN + bn + wc + j * 16,
                                    acc[i][j], GN, wmma::mem_row_major);
}

// ---------------------------------------------------------------------------
// Flash attention v7: 4 warps/CTA, each warp owns 16 q-rows x full width.
// Softmax fully in registers on S accumulator fragments (row mapping proven
// in R12-16 epilogues). P via warp-private smem strip (__syncwarp only).
// ONE __syncthreads per k-iteration (K/V handoff); prefetch after the sync.
// SMEM 96.3 KB -> 2 CTAs/SM.
// ---------------------------------------------------------------------------
#define LDQF 136   // halves per K/V/Q row (128+8)
#define LDPF 72    // halves per P row (64+8)
#define FLASH_SMEM_BYTES ((5 * 64 * LDQF + 4 * 16 * LDPF) * 2)   // 96,256 B

__global__ __launch_bounds__(128) void flash_attn()
{
    extern __shared__ __half smh[];
    __half* Qs = smh;                        // 64 x LDQF
    __half* Ks = Qs + 64 * LDQF;             // 2 x 64 x LDQF
    __half* Vs = Ks + 2 * 64 * LDQF;         // 2 x 64 x LDQF
    __half* Ps = Vs + 2 * 64 * LDQF;         // 4 x 16 x LDPF (warp-private)

    const int qb   = (gridDim.x - 1) - blockIdx.x;   // long blocks first
    const int h    = blockIdx.y;
    const int tid  = threadIdx.x;
    const int w    = tid >> 5;
    const int lane = tid & 31;
    const float scale = 0.08838834764831845f;  // 1/sqrt(128)

    const __half* Qg = g_qh + (size_t)qb * 64 * DIMSZ + h * HDIM;
    const __half* Kh = g_kh + (size_t)h * HDIM;
    const __half* Vh = g_vh + (size_t)h * HDIM;

    const int wr = w * 16;            // this warp's q-row base (0,16,32,48)
    const int r0 = lane >> 2;
    const int c0 = (lane & 3) * 2;
    __half* Pw = Ps + w * 16 * LDPF;  // warp-private P strip

    // O accumulators: 16 rows x 128 cols = 8 frags
    wmma::fragment<wmma::accumulator, 16, 16, 16, float> oacc[8];
#pragma unroll
    for (int j = 0; j < 8; j++) wmma::fill_fragment(oacc[j], 0.0f);

    // Register softmax state for the 2 rows this thread owns (r0, r0+8)
    float m_lo = -1e30f, m_hi = -1e30f;
    float l_lo = 0.0f,   l_hi = 0.0f;

    // Prologue: Q + K0/V0 (each 64x128 halves = 1024 chunks, 8/thread)
#pragma unroll
    for (int i = 0; i < 8; i++) {
        int idx = tid + i * 128;
        int r = idx >> 4, c8 = (idx & 15) << 3;
        cp16(&Qs[r * LDQF + c8], Qg + (size_t)r * DIMSZ + c8);
        cp16(&Ks[r * LDQF + c8], Kh + (size_t)r * DIMSZ + c8);
        cp16(&Vs[r * LDQF + c8], Vh + (size_t)r * DIMSZ + c8);
    }
    CP_COMMIT();

    const int rg_lo = qb * 64 + wr + r0;   // global q rows owned
    const int rg_hi = rg_lo + 8;
    const int ntiles = qb + 1;

    for (int kt = 0; kt < ntiles; kt++) {
        const int buf = kt & 1;

        CP_WAITG(0);        // current tile arrived
        __syncthreads();    // + all warps done reading buf^1 (prev iter)

        if (kt + 1 < ntiles) {
            __half* Kn = Ks + (buf ^ 1) * 64 * LDQF;
            __half* Vn = Vs + (buf ^ 1) * 64 * LDQF;
            const __half* Kg = Kh + (size_t)(kt + 1) * 64 * DIMSZ;
            const __half* Vg = Vh + (size_t)(kt + 1) * 64 * DIMSZ;
#pragma unroll
            for (int i = 0; i < 8; i++) {
                int idx = tid + i * 128;
                int r = idx >> 4, c8 = (idx & 15) << 3;
                cp16(&Kn[r * LDQF + c8], Kg + (size_t)r * DIMSZ + c8);
                cp16(&Vn[r * LDQF + c8], Vg + (size_t)r * DIMSZ + c8);
            }
            CP_COMMIT();
        }

        const __half* Kc = Ks + buf * 64 * LDQF;
        const __half* Vc = Vs + buf * 64 * LDQF;

        // S = Q[16 x 128] @ K^T[128 x 64] -> 4 acc frags
        wmma::fragment<wmma::accumulator, 16, 16, 16, float> sacc[4];
#pragma unroll
        for (int j = 0; j < 4; j++) wmma::fill_fragment(sacc[j], 0.0f);
#pragma unroll
        for (int ks = 0; ks < 8; ks++) {
            wmma::fragment<wmma::matrix_a, 16, 16, 16, __half, wmma::row_major> a;
            wmma::load_matrix_sync(a, &Qs[wr * LDQF + ks * 16], LDQF);
#pragma unroll
            for (int j = 0; j < 4; j++) {
                wmma::fragment<wmma::matrix_b, 16, 16, 16, __half, wmma::col_major> b;
                wmma::load_matrix_sync(b, &Kc[(j * 16) * LDQF + ks * 16], LDQF);
                wmma::mma_sync(sacc[j], a, b, sacc[j]);
            }
        }

        // Register softmax on sacc.
        // elem e: row = lo if (e&3)<2 else hi; col = 16j + c0 + (e&1) + 8*(e>=4)
        float mx_lo = -1e30f, mx_hi = -1e30f;
#pragma unroll
        for (int j = 0; j < 4; j++) {
#pragma unroll
            for (int e = 0; e < 8; e++) {
                bool hi = (e & 3) >= 2;
                int col_g = kt * 64 + j * 16 + c0 + (e & 1) + ((e >= 4) ? 8 : 0);
                float s = sacc[j].x[e] * scale;
                if (col_g > (hi ? rg_hi : rg_lo)) s = -1e30f;
                sacc[j].x[e] = s;
                if (hi) mx_hi = fmaxf(mx_hi, s); else mx_lo = fmaxf(mx_lo, s);
            }
        }
#pragma unroll
        for (int o = 1; o < 4; o <<= 1) {
            mx_lo = fmaxf(mx_lo, __shfl_xor_sync(0xffffffffu, mx_lo, o));
            mx_hi = fmaxf(mx_hi, __shfl_xor_sync(0xffffffffu, mx_hi, o));
        }
        float mn_lo = fmaxf(m_lo, mx_lo);
        float mn_hi = fmaxf(m_hi, mx_hi);
        float al = __expf(m_lo - mn_lo);
        float ah = __expf(m_hi - mn_hi);
        float sl = 0.0f, sh = 0.0f;
#pragma unroll
        for (int j = 0; j < 4; j++) {
#pragma unroll
            for (int e = 0; e < 8; e += 2) {
                bool hi = (e & 3) >= 2;
                float mn = hi ? mn_hi : mn_lo;
                float p0 = __expf(sacc[j].x[e] - mn);
                float p1 = __expf(sacc[j].x[e + 1] - mn);
                if (hi) sh += p0 + p1; else sl += p0 + p1;
                int row_l = r0 + (hi ? 8 : 0);
                int colp  = j * 16 + c0 + ((e >= 4) ? 8 : 0);
                *(__half2*)&Pw[row_l * LDPF + colp] = __floats2half2_rn(p0, p1);
            }
        }
#pragma unroll
        for (int o = 1; o < 4; o <<= 1) {
            sl += __shfl_xor_sync(0xffffffffu, sl, o);
            sh += __shfl_xor_sync(0xffffffffu, sh, o);
        }
        l_lo = l_lo * al + sl;
        l_hi = l_hi * ah + sh;
        m_lo = mn_lo;
        m_hi = mn_hi;

        // Rescale O accumulators (same row mapping)
#pragma unroll
        for (int j = 0; j < 8; j++)
#pragma unroll
            for (int e = 0; e < 8; e++)
                oacc[j].x[e] *= ((e & 3) >= 2) ? ah : al;

        __syncwarp();   // Pw writes visible to own warp's ldmatrix

        // O += P[16 x 64] @ V[64 x 128]
#pragma unroll
        for (int ks = 0; ks < 4; ks++) {
            wmma::fragment<wmma::matrix_a, 16, 16, 16, __half, wmma::row_major> a;
            wmma::load_matrix_sync(a, &Pw[ks * 16], LDPF);
#pragma unroll
            for (int j = 0; j < 8; j++) {
                wmma::fragment<wmma::matrix_b, 16, 16, 16, __half, wmma::row_major> b;
                wmma::load_matrix_sync(b, &Vc[(ks * 16) * LDQF + j * 16], LDQF);
                wmma::mma_sync(oacc[j], a, b, oacc[j]);
            }
        }
    }

    // Epilogue: normalize (l in registers!), store fp16 to g_oh.
    float il_lo = 1.0f / l_lo;
    float il_hi = 1.0f / l_hi;
    __half* Og = g_oh + (size_t)qb * 64 * DIMSZ + h * HDIM;
#pragma unroll
    for (int j = 0; j < 8; j++) {
#pragma unroll
        for (int e = 0; e < 8; e += 2) {
            bool hi = (e & 3) >= 2;
            float inv = hi ? il_hi : il_lo;
            float v0 = oacc[j].x[e] * inv;
            float v1 = oacc[j].x[e + 1] * inv;
            int row = wr + r0 + (hi ? 8 : 0);
            int col = j * 16 + c0 + ((e >= 4) ? 8 : 0);
            *(__half2*)&Og[(size_t)row * DIMSZ + col] = __floats2half2_rn(v0, v1);
        }
    }
}

// ---------------------------------------------------------------------------
extern "C" void kernel_launch(void* const* d_in, const int* in_sizes, int n_in,
                              void* d_out, int out_size)
{
    const float* x  = (const float*)d_in[0];
    const float* wq = (const float*)d_in[1];
    const float* wk = (const float*)d_in[2];
    const float* wv = (const float*)d_in[3];
    const float* wo = (const float*)d_in[4];
    const float* fc = (const float*)d_in[5];
    const float* fs = (const float*)d_in[6];
    float* out = (float*)d_out;

    cudaFuncSetAttribute(gemm_qkv, cudaFuncAttributeMaxDynamicSharedMemorySize,
                         GEMM_SMEM_BYTES);
    cudaFuncSetAttribute(gemm_out, cudaFuncAttributeMaxDynamicSharedMemorySize,
                         GEMM_SMEM_BYTES);
    cudaFuncSetAttribute(flash_attn, cudaFuncAttributeMaxDynamicSharedMemorySize,
                         FLASH_SMEM_BYTES);

    // 1: fused fp16 conversion (x + 4 weights)
    dim3 cgrid((W4 + 255) / 256, 1, 5);
    cvt_all<<<cgrid, 256>>>((const float4*)x, (const float4*)wq, (const float4*)wk,
                            (const float4*)wv, (const float4*)wo);

    // 2: QKV projections (R14 config) with fused rope + fp16 epilogue
    dim3 qkv_grid(GM / 128, GN / 128, 3);
    gemm_qkv<<<qkv_grid, 256, GEMM_SMEM_BYTES>>>(fc, fs);

    // 3: flash attention v7 (4 warps, register softmax)
    flash_attn<<<dim3(SEQ / 64, NHEAD), 128, FLASH_SMEM_BYTES>>>();

    // 4: output projection (R14 config; profiled control, expect ~232us)
    dim3 ogrid(GM / 128, GN / 128);
    gemm_out<<<ogrid, 256, GEMM_SMEM_BYTES>>>(out);
}